// round 2
// baseline (speedup 1.0000x reference)
#include <cuda_runtime.h>

// DynamicConv2d: B=64, C=8, H=W=256, OUT_C=8, K=3, pad=1.
// Stage 1: generate per-batch conv kernels  K[b][o][c][kh][kw] =
//          bg[c*9+kh*3+kw] + sum_i dw[b][o][i] * Wg[c*9+kh*3+kw][i]
//          (note: torch .view makes the Linear's channel index become the OUTPUT channel)
// Stage 2: grouped 3x3 conv per batch with fp32x2 packed FMA over out-channel pairs.

typedef unsigned long long u64;

#define TY 8                  // output rows per block tile
#define SIN_STRIDE 258        // 256 cols + 2 halo
#define SIN_ROWS (TY + 2)
#define SIN_PER_C (SIN_ROWS * SIN_STRIDE)
#define SMEM_W 576
#define SMEM_FLOATS (SMEM_W + 8 * SIN_PER_C)
#define SMEM_BYTES (SMEM_FLOATS * 4)

// Packed weight scratch: [b][c*9+kk][o], o fastest => out-channel pairs are
// 8-byte aligned for LDS.64 after copy to smem.
__device__ __align__(16) float g_wpack[64 * 72 * 8];

__global__ void gen_weights_kernel(const float* __restrict__ dw,
                                   const float* __restrict__ Wg,
                                   const float* __restrict__ bg) {
    int b = blockIdx.x;
    int t = threadIdx.x;          // 0..575
    int j = t >> 3;               // c*9 + kk  (0..71)
    int o = t & 7;                // output channel
    const float* dwp = dw + (b * 8 + o) * 8;
    const float* wgp = Wg + j * 8;
    float v = bg[j];
#pragma unroll
    for (int i = 0; i < 8; i++) v = fmaf(dwp[i], wgp[i], v);
    g_wpack[(b * 72 + j) * 8 + o] = v;
}

__global__ __launch_bounds__(512, 1)
void conv_kernel(const float* __restrict__ x, float* __restrict__ out) {
    extern __shared__ float sm[];
    float* sw = sm;                   // 576 floats of packed weights
    float* sin = sm + SMEM_W;         // 8 channels x 10 rows x 258 cols

    int b  = blockIdx.x >> 5;         // 32 row-tiles per batch
    int y0 = (blockIdx.x & 31) * TY;
    int tx   = threadIdx.x;           // column 0..255
    int half = threadIdx.y;           // out-channel half: 0 -> o 0..3, 1 -> o 4..7
    int tid  = tx + (half << 8);

    // --- load packed weights for this batch into smem ---
    const float* wsrc = g_wpack + b * 576;
    for (int i = tid; i < 576; i += 512) sw[i] = wsrc[i];

    // --- load input tile (with zero halo) into smem ---
    const float* xb = x + (size_t)b * (8 * 65536);
    for (int i = tid; i < 8 * SIN_PER_C; i += 512) {
        int c   = i / SIN_PER_C;
        int rem = i - c * SIN_PER_C;
        int t   = rem / SIN_STRIDE;
        int col = rem - t * SIN_STRIDE;
        int gy = y0 - 1 + t;
        int gx = col - 1;
        float v = 0.0f;
        if ((unsigned)gy < 256u && (unsigned)gx < 256u)
            v = __ldg(xb + c * 65536 + gy * 256 + gx);
        sin[i] = v;
    }
    __syncthreads();

    // --- accumulate: fp32x2 pairs over out-channel pairs ---
    u64 acc[TY][2];
#pragma unroll
    for (int r = 0; r < TY; r++) { acc[r][0] = 0ull; acc[r][1] = 0ull; }

    const u64* swq = (const u64*)sw;

#pragma unroll 1
    for (int c = 0; c < 8; c++) {
        // 18 weight pairs for this input channel & this half's 4 out channels
        u64 w[9][2];
#pragma unroll
        for (int kk = 0; kk < 9; kk++) {
#pragma unroll
            for (int p = 0; p < 2; p++)
                w[kk][p] = swq[(c * 9 + kk) * 4 + half * 2 + p];
        }
        const float* sc = sin + c * SIN_PER_C;
#pragma unroll
        for (int t = 0; t < SIN_ROWS; t++) {
            float v0 = sc[t * SIN_STRIDE + tx];
            float v1 = sc[t * SIN_STRIDE + tx + 1];
            float v2 = sc[t * SIN_STRIDE + tx + 2];
            u64 d0, d1, d2;
            unsigned u0 = __float_as_uint(v0);
            unsigned u1 = __float_as_uint(v1);
            unsigned u2 = __float_as_uint(v2);
            asm("mov.b64 %0, {%1, %1};" : "=l"(d0) : "r"(u0));
            asm("mov.b64 %0, {%1, %1};" : "=l"(d1) : "r"(u1));
            asm("mov.b64 %0, {%1, %1};" : "=l"(d2) : "r"(u2));
#pragma unroll
            for (int kh = 0; kh < 3; kh++) {
                int r = t - kh;          // output row this tap contributes to
                if (r >= 0 && r < TY) {
#pragma unroll
                    for (int p = 0; p < 2; p++) {
                        asm("fma.rn.f32x2 %0, %1, %2, %0;"
                            : "+l"(acc[r][p]) : "l"(d0), "l"(w[kh * 3 + 0][p]));
                        asm("fma.rn.f32x2 %0, %1, %2, %0;"
                            : "+l"(acc[r][p]) : "l"(d1), "l"(w[kh * 3 + 1][p]));
                        asm("fma.rn.f32x2 %0, %1, %2, %0;"
                            : "+l"(acc[r][p]) : "l"(d2), "l"(w[kh * 3 + 2][p]));
                    }
                }
            }
        }
    }

    // --- write out ---
    float* ob = out + (size_t)b * (8 * 65536);
#pragma unroll
    for (int r = 0; r < TY; r++) {
#pragma unroll
        for (int p = 0; p < 2; p++) {
            int q = half * 2 + p;       // out-channel pair index
            unsigned lo, hi;
            asm("mov.b64 {%0, %1}, %2;" : "=r"(lo), "=r"(hi) : "l"(acc[r][p]));
            ob[(2 * q + 0) * 65536 + (y0 + r) * 256 + tx] = __uint_as_float(lo);
            ob[(2 * q + 1) * 65536 + (y0 + r) * 256 + tx] = __uint_as_float(hi);
        }
    }
}

extern "C" void kernel_launch(void* const* d_in, const int* in_sizes, int n_in,
                              void* d_out, int out_size) {
    const float* x  = (const float*)d_in[0];
    const float* dw = (const float*)d_in[1];
    const float* Wg = (const float*)d_in[2];
    const float* bg = (const float*)d_in[3];
    float* out = (float*)d_out;

    cudaFuncSetAttribute(conv_kernel, cudaFuncAttributeMaxDynamicSharedMemorySize,
                         SMEM_BYTES);

    gen_weights_kernel<<<64, 576>>>(dw, Wg, bg);

    dim3 blk(256, 2, 1);
    conv_kernel<<<64 * 32, blk, SMEM_BYTES>>>(x, out);
}

// round 3
// speedup vs baseline: 1.9356x; 1.9356x over previous
#include <cuda_runtime.h>

// DynamicConv2d: B=64, C=8, H=W=256, OUT_C=8, K=3, pad=1.
// Stage 1: per-batch kernel generation (tiny GEMV).
// Stage 2: grouped 3x3 conv, fp32x2 packed FMA over out-channel pairs.
// R2: 128-col x 8-row tiles, 256 threads, 2 CTAs/SM (phase overlap),
//     vectorized LDG.128/STS.128 loader with aligned tile layout.

typedef unsigned long long u64;

#define TY 8                   // output rows per tile
#define TX 128                 // output cols per tile
#define SIN_STRIDE 136         // 128 + halo(2) + align pad; data at col 4+gx-x0
#define SIN_ROWS (TY + 2)      // 10
#define SIN_PER_C (SIN_ROWS * SIN_STRIDE)   // 1360
#define SMEM_W 576
#define SMEM_FLOATS (SMEM_W + 8 * SIN_PER_C)   // 11456
#define SMEM_BYTES (SMEM_FLOATS * 4)           // 45824

// Packed weight scratch: [b][c*9+kk][o], o fastest -> out-channel pairs are
// 8-byte aligned LDS.64 after copy to smem.
__device__ __align__(16) float g_wpack[64 * 72 * 8];

__global__ void gen_weights_kernel(const float* __restrict__ dw,
                                   const float* __restrict__ Wg,
                                   const float* __restrict__ bg) {
    int b = blockIdx.x;
    int t = threadIdx.x;          // 0..575
    int j = t >> 3;               // c*9 + kk  (0..71)
    int o = t & 7;                // output channel
    const float* dwp = dw + (b * 8 + o) * 8;
    const float* wgp = Wg + j * 8;
    float v = bg[j];
#pragma unroll
    for (int i = 0; i < 8; i++) v = fmaf(dwp[i], wgp[i], v);
    g_wpack[(b * 72 + j) * 8 + o] = v;
}

__global__ __launch_bounds__(256, 2)
void conv_kernel(const float* __restrict__ x, float* __restrict__ out) {
    extern __shared__ float sm[];
    float* sw  = sm;                  // 576 floats of packed weights
    float* sin = sm + SMEM_W;         // 8 ch x 10 rows x 136 cols

    int bi = blockIdx.x;
    int b  = bi >> 6;                 // batch
    int y0 = ((bi >> 1) & 31) * TY;   // row tile
    int x0 = (bi & 1) * TX;           // col tile
    int tx   = threadIdx.x;           // column within tile 0..127
    int half = threadIdx.y;           // out-channel half
    int tid  = tx + (half << 7);      // 0..255

    // --- weights: 576 floats = 144 float4 ---
    if (tid < 144) {
        const float4* wsrc = (const float4*)(g_wpack + b * 576);
        ((float4*)sw)[tid] = wsrc[tid];
    }

    // --- input tile: 80 rows (8c x 10t) x 32 quads, 10 passes of 256 thr ---
    const float* xb = x + (size_t)b * (8 * 65536);
    {
        int w = tid >> 5;             // 0..7  (row-in-pass)
        int j = tid & 31;             // quad index
#pragma unroll
        for (int pass = 0; pass < 10; pass++) {
            int row = pass * 8 + w;   // 0..79 = c*10 + t
            int c = row / 10;         // const-div
            int t = row - c * 10;
            int gy = y0 - 1 + t;
            float4 v = make_float4(0.f, 0.f, 0.f, 0.f);
            if ((unsigned)gy < 256u)
                v = *(const float4*)(xb + c * 65536 + gy * 256 + x0 + 4 * j);
            *(float4*)(sin + row * SIN_STRIDE + 4 + 4 * j) = v;
        }
        // halo columns: left (gx=x0-1) -> col 3, right (gx=x0+128) -> col 132
        if (tid < 160) {
            int side = tid >= 80;
            int r = side ? tid - 80 : tid;       // 0..79
            int c = r / 10;
            int t = r - c * 10;
            int gy = y0 - 1 + t;
            int gx = side ? (x0 + 128) : (x0 - 1);
            float v = 0.f;
            if (((unsigned)gy < 256u) && ((unsigned)gx < 256u))
                v = __ldg(xb + c * 65536 + gy * 256 + gx);
            sin[r * SIN_STRIDE + (side ? 132 : 3)] = v;
        }
    }
    __syncthreads();

    // --- accumulate: fp32x2 pairs over out-channel pairs ---
    u64 acc[TY][2];
#pragma unroll
    for (int r = 0; r < TY; r++) { acc[r][0] = 0ull; acc[r][1] = 0ull; }

    const u64* swq = (const u64*)sw;

#pragma unroll 1
    for (int c = 0; c < 8; c++) {
        u64 w[9][2];
#pragma unroll
        for (int kk = 0; kk < 9; kk++) {
#pragma unroll
            for (int p = 0; p < 2; p++)
                w[kk][p] = swq[(c * 9 + kk) * 4 + half * 2 + p];
        }
        const float* sc = sin + c * SIN_PER_C;
#pragma unroll
        for (int t = 0; t < SIN_ROWS; t++) {
            float v0 = sc[t * SIN_STRIDE + tx + 3];
            float v1 = sc[t * SIN_STRIDE + tx + 4];
            float v2 = sc[t * SIN_STRIDE + tx + 5];
            u64 d0, d1, d2;
            unsigned u0 = __float_as_uint(v0);
            unsigned u1 = __float_as_uint(v1);
            unsigned u2 = __float_as_uint(v2);
            asm("mov.b64 %0, {%1, %1};" : "=l"(d0) : "r"(u0));
            asm("mov.b64 %0, {%1, %1};" : "=l"(d1) : "r"(u1));
            asm("mov.b64 %0, {%1, %1};" : "=l"(d2) : "r"(u2));
#pragma unroll
            for (int kh = 0; kh < 3; kh++) {
                int r = t - kh;       // output row this tap feeds
                if (r >= 0 && r < TY) {
#pragma unroll
                    for (int p = 0; p < 2; p++) {
                        asm("fma.rn.f32x2 %0, %1, %2, %0;"
                            : "+l"(acc[r][p]) : "l"(d0), "l"(w[kh * 3 + 0][p]));
                        asm("fma.rn.f32x2 %0, %1, %2, %0;"
                            : "+l"(acc[r][p]) : "l"(d1), "l"(w[kh * 3 + 1][p]));
                        asm("fma.rn.f32x2 %0, %1, %2, %0;"
                            : "+l"(acc[r][p]) : "l"(d2), "l"(w[kh * 3 + 2][p]));
                    }
                }
            }
        }
    }

    // --- write out (coalesced per warp) ---
    float* ob = out + (size_t)b * (8 * 65536) + x0;
#pragma unroll
    for (int r = 0; r < TY; r++) {
#pragma unroll
        for (int p = 0; p < 2; p++) {
            int q = half * 2 + p;     // out-channel pair index
            unsigned lo, hi;
            asm("mov.b64 {%0, %1}, %2;" : "=r"(lo), "=r"(hi) : "l"(acc[r][p]));
            ob[(2 * q + 0) * 65536 + (y0 + r) * 256 + tx] = __uint_as_float(lo);
            ob[(2 * q + 1) * 65536 + (y0 + r) * 256 + tx] = __uint_as_float(hi);
        }
    }
}

extern "C" void kernel_launch(void* const* d_in, const int* in_sizes, int n_in,
                              void* d_out, int out_size) {
    const float* x  = (const float*)d_in[0];
    const float* dw = (const float*)d_in[1];
    const float* Wg = (const float*)d_in[2];
    const float* bg = (const float*)d_in[3];
    float* out = (float*)d_out;

    cudaFuncSetAttribute(conv_kernel, cudaFuncAttributeMaxDynamicSharedMemorySize,
                         SMEM_BYTES);

    gen_weights_kernel<<<64, 576>>>(dw, Wg, bg);

    dim3 blk(128, 2, 1);
    conv_kernel<<<64 * 32 * 2, blk, SMEM_BYTES>>>(x, out);
}